// round 3
// baseline (speedup 1.0000x reference)
#include <cuda_runtime.h>
#include <cuda_bf16.h>

// ---------------------------------------------------------------------------
// AIMNet2 interaction module.
//   Inputs (metadata order):
//     0: atomic_embedding [N, 128] f32
//     1: pairlist         [2, P]   i32   (row0 = idx_i, row1 = idx_j)
//     2: f_ij_cutoff      [P, 1]   f32
//     3: r_ij             [P, 3]   f32
//     4: W                [128,128] f32   (y = x @ W^T + b)
//     5: b                [128]    f32
//   Output: [N, 256] f32 = concat(vector_norms, radial)
//
// Algebra: transformed[p,c,g] = u[p,c] * (W @ weighted[p])[g] + b[g]
//   => one 128x128 matvec per pair, then rank-1 scatter with u.
// ---------------------------------------------------------------------------

#define FDIM 128
#define WT_STRIDE 132          // padded row stride for transposed W in smem
#define NW 8                   // warps per block (256 threads)
#define QP 8                   // pairs per warp-group
#define MAX_ATOMS 20000

#define SMEM_BYTES ((FDIM * WT_STRIDE + NW * QP * FDIM) * 4)

// Scratch (allocation-free rule: __device__ globals)
__device__ __align__(16) float g_vec[(size_t)MAX_ATOMS * 3 * FDIM];  // [N][3][128]
__device__ int g_deg[MAX_ATOMS];

__device__ __forceinline__ void red_add_v4(float* addr, float4 v) {
    asm volatile("red.global.add.v4.f32 [%0], {%1, %2, %3, %4};"
                 :: "l"(addr), "f"(v.x), "f"(v.y), "f"(v.z), "f"(v.w)
                 : "memory");
}

// ---------------------------------------------------------------------------
// Kernel 1: zero output + scratch
// ---------------------------------------------------------------------------
__global__ void zero_kernel(float4* __restrict__ out, int out4, int vec4, int n_atoms) {
    int i = blockIdx.x * blockDim.x + threadIdx.x;
    int stride = gridDim.x * blockDim.x;
    float4 z = make_float4(0.f, 0.f, 0.f, 0.f);
    for (int k = i; k < out4; k += stride) out[k] = z;
    float4* v = reinterpret_cast<float4*>(g_vec);
    for (int k = i; k < vec4; k += stride) v[k] = z;
    for (int k = i; k < n_atoms; k += stride) g_deg[k] = 0;
}

// ---------------------------------------------------------------------------
// Kernel 2: per-pair gather + weight + matvec + scatter.
// One warp processes QP=8 pairs jointly so each LDS of W^T feeds 32 FMAs.
// ---------------------------------------------------------------------------
extern "C" __global__ void __launch_bounds__(NW * 32, 2)
pair_kernel(const float* __restrict__ A,
            const int*   __restrict__ pl,
            const float* __restrict__ fc,
            const float* __restrict__ rij,
            const float* __restrict__ W,
            float*       __restrict__ out,
            int n_pairs, int n_atoms)
{
    extern __shared__ float smem[];
    float* WT = smem;                      // [128][132]: WT[f][g] = W[g][f]
    float* SW = smem + FDIM * WT_STRIDE;   // [NW][QP][128] weighted rows

    const int tid  = threadIdx.x;
    const int wid  = tid >> 5;
    const int lane = tid & 31;

    // Stage W transposed into smem (pad stride 132 -> conflict-light store,
    // conflict-free float4 reads at [f][4*lane]).
    for (int idx = tid; idx < FDIM * FDIM; idx += blockDim.x) {
        int g = idx >> 7;
        int f = idx & (FDIM - 1);
        WT[f * WT_STRIDE + g] = W[idx];
    }
    __syncthreads();

    const int* pl_i = pl;
    const int* pl_j = pl + n_pairs;
    float* sw = SW + wid * (QP * FDIM);

    const int n_groups = (n_pairs + QP - 1) / QP;
    const int gstep = gridDim.x * NW;

    for (int grp = blockIdx.x * NW + wid; grp < n_groups; grp += gstep) {
        __syncwarp();  // previous iteration's reads of sw are done

        // ---- load meta for 8 pairs (lanes 0..7) ----
        int p = grp * QP + lane;
        int valid = (lane < QP) && (p < n_pairs);
        int ii = 0, jj = 0;
        float fv = 0.f, ux = 0.f, uy = 0.f, uz = 0.f;
        if (valid) {
            ii = pl_i[p];
            jj = pl_j[p];
            fv = fc[p];
            float rx = rij[3 * p + 0];
            float ry = rij[3 * p + 1];
            float rz = rij[3 * p + 2];
            float inv = rsqrtf(rx * rx + ry * ry + rz * rz);
            ux = rx * inv; uy = ry * inv; uz = rz * inv;
        }

        // ---- gather A[j], weight by f, stage in smem, fire radial reds ----
        #pragma unroll
        for (int q = 0; q < QP; q++) {
            int   vq = __shfl_sync(0xffffffffu, valid, q);
            int   jq = __shfl_sync(0xffffffffu, jj, q);
            int   iq = __shfl_sync(0xffffffffu, ii, q);
            float fq = __shfl_sync(0xffffffffu, fv, q);
            float4 w4 = make_float4(0.f, 0.f, 0.f, 0.f);
            if (vq) {
                float4 a = *reinterpret_cast<const float4*>(A + (size_t)jq * FDIM + 4 * lane);
                w4 = make_float4(fq * a.x, fq * a.y, fq * a.z, fq * a.w);
                red_add_v4(out + (size_t)iq * (2 * FDIM) + FDIM + 4 * lane, w4);
                if (lane == 0) atomicAdd(&g_deg[iq], 1);
            }
            *reinterpret_cast<float4*>(sw + q * FDIM + 4 * lane) = w4;
        }
        __syncwarp();

        // ---- matvec: t[q][g] = sum_f w[q][f] * W[g][f], lane owns g=4l..4l+3 ----
        float4 acc[QP];
        #pragma unroll
        for (int q = 0; q < QP; q++) acc[q] = make_float4(0.f, 0.f, 0.f, 0.f);

        #pragma unroll 2
        for (int f4 = 0; f4 < FDIM / 4; f4++) {
            float4 Wv0 = *reinterpret_cast<const float4*>(WT + (4 * f4 + 0) * WT_STRIDE + 4 * lane);
            float4 Wv1 = *reinterpret_cast<const float4*>(WT + (4 * f4 + 1) * WT_STRIDE + 4 * lane);
            float4 Wv2 = *reinterpret_cast<const float4*>(WT + (4 * f4 + 2) * WT_STRIDE + 4 * lane);
            float4 Wv3 = *reinterpret_cast<const float4*>(WT + (4 * f4 + 3) * WT_STRIDE + 4 * lane);
            #pragma unroll
            for (int q = 0; q < QP; q++) {
                float4 wq = *reinterpret_cast<const float4*>(sw + q * FDIM + 4 * f4);
                acc[q].x = fmaf(wq.x, Wv0.x, acc[q].x);
                acc[q].y = fmaf(wq.x, Wv0.y, acc[q].y);
                acc[q].z = fmaf(wq.x, Wv0.z, acc[q].z);
                acc[q].w = fmaf(wq.x, Wv0.w, acc[q].w);
                acc[q].x = fmaf(wq.y, Wv1.x, acc[q].x);
                acc[q].y = fmaf(wq.y, Wv1.y, acc[q].y);
                acc[q].z = fmaf(wq.y, Wv1.z, acc[q].z);
                acc[q].w = fmaf(wq.y, Wv1.w, acc[q].w);
                acc[q].x = fmaf(wq.z, Wv2.x, acc[q].x);
                acc[q].y = fmaf(wq.z, Wv2.y, acc[q].y);
                acc[q].z = fmaf(wq.z, Wv2.z, acc[q].z);
                acc[q].w = fmaf(wq.z, Wv2.w, acc[q].w);
                acc[q].x = fmaf(wq.w, Wv3.x, acc[q].x);
                acc[q].y = fmaf(wq.w, Wv3.y, acc[q].y);
                acc[q].z = fmaf(wq.w, Wv3.z, acc[q].z);
                acc[q].w = fmaf(wq.w, Wv3.w, acc[q].w);
            }
        }

        // ---- scatter vec[i][c][:] += u[c] * t[:] ----
        #pragma unroll
        for (int q = 0; q < QP; q++) {
            int vq = __shfl_sync(0xffffffffu, valid, q);   // uniform across warp
            int iq = __shfl_sync(0xffffffffu, ii, q);
            float uxq = __shfl_sync(0xffffffffu, ux, q);
            float uyq = __shfl_sync(0xffffffffu, uy, q);
            float uzq = __shfl_sync(0xffffffffu, uz, q);
            if (!vq) continue;
            float* vb = g_vec + (size_t)iq * (3 * FDIM) + 4 * lane;
            float4 t = acc[q];
            red_add_v4(vb,
                       make_float4(uxq * t.x, uxq * t.y, uxq * t.z, uxq * t.w));
            red_add_v4(vb + FDIM,
                       make_float4(uyq * t.x, uyq * t.y, uyq * t.z, uyq * t.w));
            red_add_v4(vb + 2 * FDIM,
                       make_float4(uzq * t.x, uzq * t.y, uzq * t.z, uzq * t.w));
        }
    }
}

// ---------------------------------------------------------------------------
// Kernel 3: finalize — add deg*b bias, norm over 3 components, write out[:, :128]
// ---------------------------------------------------------------------------
__global__ void finalize_kernel(const float* __restrict__ bvec,
                                float* __restrict__ out, int n_atoms) {
    int t = blockIdx.x * blockDim.x + threadIdx.x;
    int total = n_atoms * 32;
    if (t >= total) return;
    int atom = t >> 5;
    int l = t & 31;

    const float* vb = g_vec + (size_t)atom * (3 * FDIM) + 4 * l;
    float4 vx = *reinterpret_cast<const float4*>(vb);
    float4 vy = *reinterpret_cast<const float4*>(vb + FDIM);
    float4 vz = *reinterpret_cast<const float4*>(vb + 2 * FDIM);

    float d = (float)g_deg[atom];
    float4 bb = *reinterpret_cast<const float4*>(bvec + 4 * l);
    vx.x += d * bb.x; vx.y += d * bb.y; vx.z += d * bb.z; vx.w += d * bb.w;
    vy.x += d * bb.x; vy.y += d * bb.y; vy.z += d * bb.z; vy.w += d * bb.w;
    vz.x += d * bb.x; vz.y += d * bb.y; vz.z += d * bb.z; vz.w += d * bb.w;

    float4 r;
    r.x = sqrtf(vx.x * vx.x + vy.x * vy.x + vz.x * vz.x + 1e-12f);
    r.y = sqrtf(vx.y * vx.y + vy.y * vy.y + vz.y * vz.y + 1e-12f);
    r.z = sqrtf(vx.z * vx.z + vy.z * vy.z + vz.z * vz.z + 1e-12f);
    r.w = sqrtf(vx.w * vx.w + vy.w * vy.w + vz.w * vz.w + 1e-12f);

    *reinterpret_cast<float4*>(out + (size_t)atom * (2 * FDIM) + 4 * l) = r;
}

// ---------------------------------------------------------------------------
extern "C" void kernel_launch(void* const* d_in, const int* in_sizes, int n_in,
                              void* d_out, int out_size) {
    const float* A   = (const float*)d_in[0];
    const int*   pl  = (const int*)d_in[1];
    const float* fc  = (const float*)d_in[2];
    const float* rij = (const float*)d_in[3];
    const float* W   = (const float*)d_in[4];
    const float* b   = (const float*)d_in[5];
    float* out = (float*)d_out;

    int n_atoms = in_sizes[0] / FDIM;
    int n_pairs = in_sizes[2];

    cudaFuncSetAttribute(pair_kernel,
                         cudaFuncAttributeMaxDynamicSharedMemorySize, SMEM_BYTES);

    int out4 = out_size / 4;
    int vec4 = n_atoms * (3 * FDIM) / 4;
    zero_kernel<<<2048, 256>>>((float4*)out, out4, vec4, n_atoms);

    pair_kernel<<<592, NW * 32, SMEM_BYTES>>>(A, pl, fc, rij, W, out,
                                              n_pairs, n_atoms);

    int fin_threads = n_atoms * 32;
    finalize_kernel<<<(fin_threads + 255) / 256, 256>>>(b, out, n_atoms);
}

// round 7
// speedup vs baseline: 2.0855x; 2.0855x over previous
#include <cuda_runtime.h>
#include <cuda_bf16.h>

// ---------------------------------------------------------------------------
// AIMNet2 interaction module — per-atom formulation.
//
//   radial[i]   = Σ_{p∈i} f_p * A[j_p]                       (segment sum)
//   s[i,c,:]    = Σ_{p∈i} u[p,c] * f_p * A[j_p]              (segment sum)
//   vec[i,c,:]  = W @ s[i,c,:] + deg(i)*b                    (3 matvecs/atom)
//   out[i]      = [ sqrt(Σ_c vec²+1e-12), radial ]
//
// Pipeline: histogram by idx_i -> prefix scan -> scatter pair ids ->
//           main kernel (1 warp per atom: register segment-sum + packed
//           f32x2 matvec). No atomics on the feature data, no big scratch.
// ---------------------------------------------------------------------------

#define FDIM 128
#define WT_S 132                 // floats, padded row stride for W^T in smem
#define S2_S 132                 // ull stride per component row
#define MAX_ATOMS 20480
#define MAX_PAIRS 393216
#define MAIN_BLOCKS 296          // 2 per SM, all warps resident
#define MAIN_WARPS (MAIN_BLOCKS * 8)

typedef unsigned long long ull;

__device__ int g_count[MAX_ATOMS + 1];
__device__ int g_start[MAX_ATOMS + 1];
__device__ int g_cursor[MAX_ATOMS + 1];
__device__ int g_sorted[MAX_PAIRS];

__device__ __forceinline__ ull dup2(float v) {
    ull d; asm("mov.b64 %0, {%1, %1};" : "=l"(d) : "f"(v)); return d;
}
__device__ __forceinline__ ull pack2(float lo, float hi) {
    ull d; asm("mov.b64 %0, {%1, %2};" : "=l"(d) : "f"(lo), "f"(hi)); return d;
}
__device__ __forceinline__ void unpack2(ull v, float& lo, float& hi) {
    asm("mov.b64 {%0, %1}, %2;" : "=f"(lo), "=f"(hi) : "l"(v));
}
#define FMA2(acc, a, b) \
    asm("fma.rn.f32x2 %0, %1, %2, %0;" : "+l"(acc) : "l"(a), "l"(b))

// ---------------------------------------------------------------------------
__global__ void zero_counts_kernel(int n_atoms) {
    int i = blockIdx.x * blockDim.x + threadIdx.x;
    if (i <= n_atoms) g_count[i] = 0;
}

__global__ void hist_kernel(const int* __restrict__ pl, int n_pairs) {
    int p = blockIdx.x * blockDim.x + threadIdx.x;
    if (p < n_pairs) atomicAdd(&g_count[pl[p]], 1);
}

// Single-block scan over counts -> g_start (exclusive) and g_cursor copy.
__global__ void scan_kernel(int n_atoms) {
    __shared__ int sm[1024];
    __shared__ int carry_s;
    int tid = threadIdx.x;
    if (tid == 0) carry_s = 0;
    __syncthreads();
    for (int base = 0; base < n_atoms; base += 1024) {
        int idx = base + tid;
        int v = (idx < n_atoms) ? g_count[idx] : 0;
        sm[tid] = v;
        __syncthreads();
        for (int off = 1; off < 1024; off <<= 1) {
            int t = (tid >= off) ? sm[tid - off] : 0;
            __syncthreads();
            sm[tid] += t;
            __syncthreads();
        }
        int carry = carry_s;
        int excl = carry + sm[tid] - v;
        if (idx < n_atoms) { g_start[idx] = excl; g_cursor[idx] = excl; }
        int tot = sm[1023];
        __syncthreads();
        if (tid == 0) carry_s = carry + tot;
        __syncthreads();
    }
    if (tid == 0) g_start[n_atoms] = carry_s;
}

__global__ void scatter_kernel(const int* __restrict__ pl, int n_pairs) {
    int p = blockIdx.x * blockDim.x + threadIdx.x;
    if (p < n_pairs) {
        int pos = atomicAdd(&g_cursor[pl[p]], 1);
        g_sorted[pos] = p;
    }
}

// ---------------------------------------------------------------------------
// Main kernel: one warp per atom (grid-stride). Lane owns features/outputs
// g = 4*lane .. 4*lane+3.
// ---------------------------------------------------------------------------
__global__ void __launch_bounds__(256, 2)
main_kernel(const float* __restrict__ A,
            const int*   __restrict__ pl,
            const float* __restrict__ fc,
            const float* __restrict__ rij,
            const float* __restrict__ W,
            const float* __restrict__ bvec,
            float*       __restrict__ out,
            int n_pairs, int n_atoms)
{
    extern __shared__ float smem[];
    float* WT = smem;                               // [128][WT_S] : WT[f][g] = W[g][f]
    ull* S2   = (ull*)(smem + FDIM * WT_S);         // [8 warps][3][S2_S] duplicated pairs

    const int tid  = threadIdx.x;
    const int wid  = tid >> 5;
    const int lane = tid & 31;

    for (int idx = tid; idx < FDIM * FDIM; idx += 256) {
        int g = idx >> 7, f = idx & (FDIM - 1);
        WT[f * WT_S + g] = W[idx];
    }
    __syncthreads();

    ull* s2w = S2 + wid * 3 * S2_S;
    const int* pl_j = pl + n_pairs;
    const int fbase = 4 * lane;

    for (int atom = blockIdx.x * 8 + wid; atom < n_atoms; atom += MAIN_WARPS) {
        const int s0 = g_start[atom];
        const int s1 = g_start[atom + 1];

        // ---- register segment-sum over this atom's pairs ----
        float4 racc = make_float4(0.f, 0.f, 0.f, 0.f);
        float4 sx   = racc, sy = racc, sz = racc;

        for (int base = s0; base < s1; base += 32) {
            int m = s1 - base; if (m > 32) m = 32;
            int jj = 0; float fq = 0.f, ux = 0.f, uy = 0.f, uz = 0.f;
            if (lane < m) {
                int pid = g_sorted[base + lane];
                jj = pl_j[pid];
                fq = __ldg(fc + pid);
                float rx = __ldg(rij + 3 * pid + 0);
                float ry = __ldg(rij + 3 * pid + 1);
                float rz = __ldg(rij + 3 * pid + 2);
                float inv = rsqrtf(rx * rx + ry * ry + rz * rz);
                ux = rx * inv; uy = ry * inv; uz = rz * inv;
            }
            for (int q = 0; q < m; q++) {
                int   j  = __shfl_sync(0xffffffffu, jj, q);
                float f_ = __shfl_sync(0xffffffffu, fq, q);
                float x  = __shfl_sync(0xffffffffu, ux, q);
                float y  = __shfl_sync(0xffffffffu, uy, q);
                float z  = __shfl_sync(0xffffffffu, uz, q);
                float4 a = *reinterpret_cast<const float4*>(A + (size_t)j * FDIM + fbase);
                float4 w = make_float4(f_ * a.x, f_ * a.y, f_ * a.z, f_ * a.w);
                racc.x += w.x; racc.y += w.y; racc.z += w.z; racc.w += w.w;
                sx.x = fmaf(x, w.x, sx.x); sx.y = fmaf(x, w.y, sx.y);
                sx.z = fmaf(x, w.z, sx.z); sx.w = fmaf(x, w.w, sx.w);
                sy.x = fmaf(y, w.x, sy.x); sy.y = fmaf(y, w.y, sy.y);
                sy.z = fmaf(y, w.z, sy.z); sy.w = fmaf(y, w.w, sy.w);
                sz.x = fmaf(z, w.x, sz.x); sz.y = fmaf(z, w.y, sz.y);
                sz.z = fmaf(z, w.z, sz.z); sz.w = fmaf(z, w.w, sz.w);
            }
        }

        // radial half of the output
        *reinterpret_cast<float4*>(out + (size_t)atom * (2 * FDIM) + FDIM + fbase) = racc;

        // ---- stage s duplicated ({v,v}) for packed broadcast reads ----
        __syncwarp();   // prior atom's matvec reads of s2w are done
        s2w[0 * S2_S + fbase + 0] = dup2(sx.x);
        s2w[0 * S2_S + fbase + 1] = dup2(sx.y);
        s2w[0 * S2_S + fbase + 2] = dup2(sx.z);
        s2w[0 * S2_S + fbase + 3] = dup2(sx.w);
        s2w[1 * S2_S + fbase + 0] = dup2(sy.x);
        s2w[1 * S2_S + fbase + 1] = dup2(sy.y);
        s2w[1 * S2_S + fbase + 2] = dup2(sy.z);
        s2w[1 * S2_S + fbase + 3] = dup2(sy.w);
        s2w[2 * S2_S + fbase + 0] = dup2(sz.x);
        s2w[2 * S2_S + fbase + 1] = dup2(sz.y);
        s2w[2 * S2_S + fbase + 2] = dup2(sz.z);
        s2w[2 * S2_S + fbase + 3] = dup2(sz.w);
        __syncwarp();

        // ---- 3 matvecs with packed f32x2: t[c][g] = sum_f s[c][f] * W[g][f] ----
        ull a00 = 0, a01 = 0, a10 = 0, a11 = 0, a20 = 0, a21 = 0;
        #pragma unroll 8
        for (int f = 0; f < FDIM; f++) {
            float4 Wv = *reinterpret_cast<const float4*>(WT + f * WT_S + fbase);
            ull wp0 = pack2(Wv.x, Wv.y);
            ull wp1 = pack2(Wv.z, Wv.w);
            ull sb0 = s2w[0 * S2_S + f];
            ull sb1 = s2w[1 * S2_S + f];
            ull sb2 = s2w[2 * S2_S + f];
            FMA2(a00, sb0, wp0); FMA2(a01, sb0, wp1);
            FMA2(a10, sb1, wp0); FMA2(a11, sb1, wp1);
            FMA2(a20, sb2, wp0); FMA2(a21, sb2, wp1);
        }

        // ---- bias + norm + store ----
        float tx[4], ty[4], tz[4];
        unpack2(a00, tx[0], tx[1]); unpack2(a01, tx[2], tx[3]);
        unpack2(a10, ty[0], ty[1]); unpack2(a11, ty[2], ty[3]);
        unpack2(a20, tz[0], tz[1]); unpack2(a21, tz[2], tz[3]);

        float deg = (float)(s1 - s0);
        float4 bb = __ldg(reinterpret_cast<const float4*>(bvec + fbase));
        float bbv[4] = {bb.x, bb.y, bb.z, bb.w};

        float4 nrm;
        float* nv = &nrm.x;
        #pragma unroll
        for (int k = 0; k < 4; k++) {
            float db = deg * bbv[k];
            float vx = tx[k] + db;
            float vy = ty[k] + db;
            float vz = tz[k] + db;
            nv[k] = sqrtf(vx * vx + vy * vy + vz * vz + 1e-12f);
        }
        *reinterpret_cast<float4*>(out + (size_t)atom * (2 * FDIM) + fbase) = nrm;
    }
}

// ---------------------------------------------------------------------------
extern "C" void kernel_launch(void* const* d_in, const int* in_sizes, int n_in,
                              void* d_out, int out_size) {
    const float* A   = (const float*)d_in[0];
    const int*   pl  = (const int*)d_in[1];
    const float* fc  = (const float*)d_in[2];
    const float* rij = (const float*)d_in[3];
    const float* W   = (const float*)d_in[4];
    const float* b   = (const float*)d_in[5];
    float* out = (float*)d_out;

    int n_atoms = in_sizes[0] / FDIM;
    int n_pairs = in_sizes[2];

    static int smem_set = 0;
    const int SMEM_MAIN = FDIM * WT_S * 4 + 8 * 3 * S2_S * 8;   // 92,928 B
    if (!smem_set) {
        cudaFuncSetAttribute(main_kernel,
                             cudaFuncAttributeMaxDynamicSharedMemorySize, SMEM_MAIN);
        smem_set = 1;
    }

    int pb = (n_pairs + 255) / 256;
    zero_counts_kernel<<<(n_atoms + 256) / 256, 256>>>(n_atoms);
    hist_kernel<<<pb, 256>>>(pl, n_pairs);
    scan_kernel<<<1, 1024>>>(n_atoms);
    scatter_kernel<<<pb, 256>>>(pl, n_pairs);
    main_kernel<<<MAIN_BLOCKS, 256, SMEM_MAIN>>>(A, pl, fc, rij, W, b, out,
                                                 n_pairs, n_atoms);
}